// round 15
// baseline (speedup 1.0000x reference)
#include <cuda_runtime.h>
#include <math.h>

#define D_FEAT 128
#define FULL 0xffffffffu

__device__ __forceinline__ unsigned f2ord(float f) {
    unsigned u = __float_as_uint(f);
    return (u & 0x80000000u) ? ~u : (u | 0x80000000u);
}

__device__ __forceinline__ float dot4(float4 v, float4 c) {
    return v.x * c.x + v.y * c.y + v.z * c.z + v.w * c.w;
}

// Transpose-reduce 8 partials: returns on lane l the full 32-lane sum of
// original p[(l>>2)&7]. 9 shuffles, depth 5.
__device__ __forceinline__ float reduce8(float (&p)[8], bool h16, bool h8, bool h4) {
#pragma unroll
    for (int i = 0; i < 4; i++) {
        float send = h16 ? p[i] : p[i + 4];
        float recv = __shfl_xor_sync(FULL, send, 16);
        p[i] = (h16 ? p[i + 4] : p[i]) + recv;
    }
#pragma unroll
    for (int i = 0; i < 2; i++) {
        float send = h8 ? p[i] : p[i + 2];
        float recv = __shfl_xor_sync(FULL, send, 8);
        p[i] = (h8 ? p[i + 2] : p[i]) + recv;
    }
    {
        float send = h4 ? p[0] : p[1];
        float recv = __shfl_xor_sync(FULL, send, 4);
        p[0] = (h4 ? p[1] : p[0]) + recv;
    }
    p[0] += __shfl_xor_sync(FULL, p[0], 2);
    p[0] += __shfl_xor_sync(FULL, p[0], 1);
    return p[0];
}

// One selection step: pick current max key (lowest lane on ties), add to mask,
// knock out the winner.
__device__ __forceinline__ void sel_step(unsigned& key, unsigned& sel, int lane) {
    unsigned m = __reduce_max_sync(FULL, key);
    unsigned b = __ballot_sync(FULL, key == m);
    int kk = __ffs(b) - 1;
    sel |= 1u << kk;
    if (lane == kk) key = 0u;
}

// ---------------------------------------------------------------------------
// K==32 fast path: ONE BLOCK (128 threads, 4 warps) PER BATCH NODE.
// Each neighbor row is read from L2 exactly once: warp w loads its 8 rows,
// computes dot+selfdot partials from registers, and parks the row in smem.
// The mean phase reads the 10 selected rows from smem — zero L2 re-gather.
// Norms come free from the self-dot tree; no precompute kernel at all.
// ---------------------------------------------------------------------------
__global__ void __launch_bounds__(128) agg_block_kernel(
    const float* __restrict__ feats,
    const int* __restrict__ nodes,
    const int* __restrict__ neighs,
    const int* __restrict__ ns_ptr,
    float* __restrict__ out, int B)
{
    __shared__ float4 s_rows[32][32];   // [neighbor][float4 chunk] = 16KB
    __shared__ float s_sims[32];

    int b = blockIdx.x;
    if (b >= B) return;
    int tid = threadIdx.x;
    int w = tid >> 5;
    int lane = tid & 31;

    int ns = ns_ptr ? __ldg(ns_ptr) : 10;
    if (ns > 32) ns = 32;
    if (ns < 1) ns = 1;

    int node = __ldg(&nodes[b]);
    float4 c = ((const float4*)(feats + (size_t)node * D_FEAT))[lane];
    // center norm (same 512B line for all 4 warps -> L1 broadcast)
    float cd = dot4(c, c);
#pragma unroll
    for (int o = 16; o; o >>= 1) cd += __shfl_xor_sync(FULL, cd, o);
    float cnorm = sqrtf(cd);

    // warp w owns neighbors 8w..8w+7 (2 uniform LDG.128 for the indices)
    const int4* nb = (const int4*)(neighs + (size_t)b * 32);
    int4 ia = __ldg(&nb[2 * w]);
    int4 ib = __ldg(&nb[2 * w + 1]);
    int idxs[8] = {ia.x, ia.y, ia.z, ia.w, ib.x, ib.y, ib.z, ib.w};

    float p[8], q[8];
#pragma unroll
    for (int j = 0; j < 8; j++) {
        float4 v = ((const float4*)(feats + (size_t)idxs[j] * D_FEAT))[lane];
        p[j] = dot4(v, c);   // dot partial
        q[j] = dot4(v, v);   // self-dot partial (norm, free: v already in regs)
        s_rows[8 * w + j][lane] = v;   // park row for the mean phase
    }
    bool h16 = (lane & 16) != 0;
    bool h8  = (lane & 8)  != 0;
    bool h4  = (lane & 4)  != 0;
    float rP = reduce8(p, h16, h8, h4);
    float rQ = reduce8(q, h16, h8, h4);
    // lane l holds sums for neighbor 8w + ((l>>2)&7); lanes 4j..4j+3 agree.
    float sim = rP / (cnorm * sqrtf(rQ));
    if ((lane & 3) == 0) s_sims[8 * w + (lane >> 2)] = sim;
    __syncthreads();   // rows + sims visible block-wide

    // selection (redundant per warp — avoids a second barrier).
    // s_sims is in canonical neighbor order: lowest-index tie-break == top_k.
    unsigned key = f2ord(s_sims[lane]);
    unsigned sel = 0u;
    for (int i = 0; i < ns; i++) sel_step(key, sel, lane);

    // mean + relu: thread t accumulates feature element t over selected rows.
    // srf[k*128 + t]: consecutive threads hit consecutive banks (conflict-free).
    const float* srf = (const float*)s_rows;
    float acc = 0.0f;
    unsigned m2 = sel;
    while (m2) {
        int k = __ffs(m2) - 1;
        m2 &= m2 - 1;
        acc += srf[k * 128 + tid];
    }
    out[(size_t)b * D_FEAT + tid] = fmaxf(acc / (float)ns, 0.0f);
}

// ---------------------------------------------------------------------------
// Generic fallback (K != 32): warp per node, inline norms, global re-gather.
// ---------------------------------------------------------------------------
__global__ void __launch_bounds__(256) agg_generic_kernel(
    const float* __restrict__ feats,
    const int* __restrict__ nodes,
    const int* __restrict__ neighs,
    const int* __restrict__ ns_ptr,
    float* __restrict__ out, int B, int K)
{
    int warp = (blockIdx.x * blockDim.x + threadIdx.x) >> 5;
    int lane = threadIdx.x & 31;
    if (warp >= B) return;

    int ns = ns_ptr ? __ldg(ns_ptr) : 10;
    if (ns > K) ns = K;
    if (ns < 1) ns = 1;

    int node = __ldg(&nodes[warp]);
    float4 c = ((const float4*)(feats + (size_t)node * D_FEAT))[lane];
    float cd = dot4(c, c);
#pragma unroll
    for (int o = 16; o; o >>= 1) cd += __shfl_xor_sync(FULL, cd, o);
    float cnorm = sqrtf(cd);

    int myneigh = (lane < K) ? __ldg(&neighs[(size_t)warp * K + lane]) : 0;
    float mydot = 0.0f, myq = 1.0f;
    for (int k = 0; k < K; k++) {
        int idx = __shfl_sync(FULL, myneigh, k);
        float4 v = ((const float4*)(feats + (size_t)idx * D_FEAT))[lane];
        float pp = dot4(v, c);
        float qq = dot4(v, v);
#pragma unroll
        for (int o = 16; o; o >>= 1) {
            pp += __shfl_xor_sync(FULL, pp, o);
            qq += __shfl_xor_sync(FULL, qq, o);
        }
        if (lane == k) { mydot = pp; myq = qq; }
    }
    float sim = mydot / (cnorm * sqrtf(myq));

    unsigned key = f2ord(sim);
    if (lane >= K) key = 0u;
    unsigned sel = 0u;
    for (int i = 0; i < ns; i++) sel_step(key, sel, lane);

    float4 acc = make_float4(0.f, 0.f, 0.f, 0.f);
    unsigned m2 = sel;
    while (m2) {
        int k = __ffs(m2) - 1;
        m2 &= m2 - 1;
        int idx = __shfl_sync(FULL, myneigh, k);
        float4 v = ((const float4*)(feats + (size_t)idx * D_FEAT))[lane];
        acc.x += v.x; acc.y += v.y; acc.z += v.z; acc.w += v.w;
    }
    float inv = 1.0f / (float)ns;
    float4 o;
    o.x = fmaxf(acc.x * inv, 0.0f);
    o.y = fmaxf(acc.y * inv, 0.0f);
    o.z = fmaxf(acc.z * inv, 0.0f);
    o.w = fmaxf(acc.w * inv, 0.0f);
    ((float4*)(out + (size_t)warp * D_FEAT))[lane] = o;
}

// ---------------------------------------------------------------------------
// kernel_launch: graph-capturable, allocation-free. Single kernel now.
// ---------------------------------------------------------------------------
extern "C" void kernel_launch(void* const* d_in, const int* in_sizes, int n_in,
                              void* d_out, int out_size) {
    const float* feats = (const float*)d_in[0];
    const int* nodes = (const int*)d_in[1];
    const int* neighs = (const int*)d_in[2];
    const int* ns_ptr = (n_in > 3) ? (const int*)d_in[3] : nullptr;

    int B = in_sizes[1];
    int K = (B > 0) ? (in_sizes[2] / B) : 0;

    if (K == 32) {
        agg_block_kernel<<<B, 128>>>(feats, nodes, neighs, ns_ptr,
                                     (float*)d_out, B);
    } else {
        int agg_blocks = (B * 32 + 255) / 256;
        agg_generic_kernel<<<agg_blocks, 256>>>(feats, nodes, neighs, ns_ptr,
                                                (float*)d_out, B, K);
    }
}